// round 11
// baseline (speedup 1.0000x reference)
#include <cuda_runtime.h>
#include <cuda_fp16.h>
#include <cstdint>

// Problem constants
#define NN 100000
#define EE 1600000
#define NFEAT 256
#define NHID 128
#define LATENT 64
#define SCAN_CHUNK 2048
#define NTOT (NN + 1)
#define NSCANBLK ((NTOT + SCAN_CHUNK - 1) / SCAN_CHUNK)

// Scratch (allocation-free rule: __device__ globals)
__device__ __half g_sup[(size_t)NN * NHID];    // fp16 support (gemm out -> spmm in)
__device__ __half g_h[(size_t)NN * NHID];      // fp16 h1/h2 (spmm out -> gemm in)
__device__ __half g_w1t[NHID * NFEAT];         // W1^T [128,256] fp16
__device__ __half g_w2t[NHID * NHID];          // W2^T [128,128] fp16
__device__ __half g_wct[NHID * NHID];          // [mu|lv]^T [128,128] fp16
__device__ float  g_bcatf[NHID];
__device__ int    g_cnt[NN];
__device__ int    g_rowptr[NTOT];
__device__ int    g_blocksums[NSCANBLK + 1];
__device__ int    g_colS[EE];
__device__ float  g_wS[EE];

// ===========================================================================
// mma.sync helpers
// ===========================================================================
__device__ __forceinline__ uint32_t smem_to_u32(const void* p) {
    uint32_t a;
    asm("{ .reg .u64 t; cvta.to.shared.u64 t, %1; cvt.u32.u64 %0, t; }"
        : "=r"(a) : "l"(p));
    return a;
}

__device__ __forceinline__ void ldsm_x4(uint32_t& r0, uint32_t& r1,
                                        uint32_t& r2, uint32_t& r3, uint32_t addr)
{
    asm volatile("ldmatrix.sync.aligned.m8n8.x4.shared.b16 {%0,%1,%2,%3}, [%4];"
                 : "=r"(r0), "=r"(r1), "=r"(r2), "=r"(r3) : "r"(addr));
}

__device__ __forceinline__ void mma16816(float* c, const uint32_t* a, const uint32_t* b)
{
    asm volatile(
        "mma.sync.aligned.m16n8k16.row.col.f32.f16.f16.f32 "
        "{%0,%1,%2,%3}, {%4,%5,%6,%7}, {%8,%9}, {%0,%1,%2,%3};"
        : "+f"(c[0]), "+f"(c[1]), "+f"(c[2]), "+f"(c[3])
        : "r"(a[0]), "r"(a[1]), "r"(a[2]), "r"(a[3]), "r"(b[0]), "r"(b[1]));
}

// ===========================================================================
// HMMA GEMM: C[M,128] = A[M,KDIM] @ Bt[128,KDIM]^T, fp32 acc. (unchanged)
// ===========================================================================
#define ROWP 24

template <int KDIM, bool HEADS, bool AFP32>
__global__ __launch_bounds__(256) void mma_gemm(
    const void* __restrict__ Av, const __half* __restrict__ Bt,
    const float* __restrict__ bias, void* __restrict__ outv, int M)
{
    __shared__ __align__(16) __half sA[128 * ROWP];
    __shared__ __align__(16) __half sB[128 * ROWP];

    const int tid  = threadIdx.x;
    const int warp = tid >> 5, lane = tid & 31;
    const int warpM = (warp >> 1) * 32;
    const int warpN = (warp & 1) * 64;
    const int blockRow = blockIdx.x * 128;

    const uint32_t sAb = smem_to_u32(sA);
    const uint32_t sBb = smem_to_u32(sB);

    float acc[2][8][4];
#pragma unroll
    for (int i = 0; i < 2; i++)
#pragma unroll
        for (int j = 0; j < 8; j++)
#pragma unroll
            for (int k = 0; k < 4; k++) acc[i][j][k] = 0.f;

    const int ldRow = tid >> 1;
    const int ldChunk = (tid & 1) * 8;
    const int gRowA = blockRow + ldRow;

    const uint32_t aOffBase =
        (uint32_t)(warpM + (lane & 15)) * (ROWP * 2) + (uint32_t)((lane >> 4) * 16);
    const uint32_t bOffBase =
        (uint32_t)(warpN + ((lane >> 4) << 3) + (lane & 7)) * (ROWP * 2)
        + (uint32_t)(((lane >> 3) & 1) * 16);

#pragma unroll 1
    for (int k0 = 0; k0 < KDIM; k0 += 16) {
        uint4 va = make_uint4(0u, 0u, 0u, 0u);
        if (gRowA < M) {
            if (AFP32) {
                const float* A32 = (const float*)Av;
                float4 f0 = *reinterpret_cast<const float4*>(A32 + (size_t)gRowA * KDIM + k0 + ldChunk);
                float4 f1 = *reinterpret_cast<const float4*>(A32 + (size_t)gRowA * KDIM + k0 + ldChunk + 4);
                __half2 p0 = __floats2half2_rn(f0.x, f0.y);
                __half2 p1 = __floats2half2_rn(f0.z, f0.w);
                __half2 p2 = __floats2half2_rn(f1.x, f1.y);
                __half2 p3 = __floats2half2_rn(f1.z, f1.w);
                va.x = *reinterpret_cast<uint32_t*>(&p0);
                va.y = *reinterpret_cast<uint32_t*>(&p1);
                va.z = *reinterpret_cast<uint32_t*>(&p2);
                va.w = *reinterpret_cast<uint32_t*>(&p3);
            } else {
                const __half* A16 = (const __half*)Av;
                va = *reinterpret_cast<const uint4*>(A16 + (size_t)gRowA * KDIM + k0 + ldChunk);
            }
        }
        *reinterpret_cast<uint4*>(sA + ldRow * ROWP + ldChunk) = va;
        uint4 vb = *reinterpret_cast<const uint4*>(Bt + (size_t)ldRow * KDIM + k0 + ldChunk);
        *reinterpret_cast<uint4*>(sB + ldRow * ROWP + ldChunk) = vb;
        __syncthreads();

        uint32_t af[2][4];
#pragma unroll
        for (int mi = 0; mi < 2; mi++)
            ldsm_x4(af[mi][0], af[mi][1], af[mi][2], af[mi][3],
                    sAb + aOffBase + (uint32_t)mi * 16 * (ROWP * 2));

        uint32_t bf[8][2];
#pragma unroll
        for (int nj = 0; nj < 4; nj++) {
            uint32_t b0, b1, b2, b3;
            ldsm_x4(b0, b1, b2, b3,
                    sBb + bOffBase + (uint32_t)nj * 16 * (ROWP * 2));
            bf[nj * 2][0] = b0;     bf[nj * 2][1] = b1;
            bf[nj * 2 + 1][0] = b2; bf[nj * 2 + 1][1] = b3;
        }

#pragma unroll
        for (int mi = 0; mi < 2; mi++)
#pragma unroll
            for (int ni = 0; ni < 8; ni++)
                mma16816(acc[mi][ni], af[mi], bf[ni]);
        __syncthreads();
    }

    const int g = lane >> 2, tg = lane & 3;
#pragma unroll
    for (int mi = 0; mi < 2; mi++) {
        int r0 = blockRow + warpM + mi * 16 + g;
#pragma unroll
        for (int ni = 0; ni < 8; ni++) {
            int col = warpN + ni * 8 + tg * 2;
            if (HEADS) {
                float* out = reinterpret_cast<float*>(outv);
                size_t regionOff = (col < LATENT) ? 0 : (size_t)NN * LATENT;
                int c0 = col & (LATENT - 1);
                float bx = bias[col], by = bias[col + 1];
                if (r0 < M) {
                    float2 v = make_float2(acc[mi][ni][0] + bx, acc[mi][ni][1] + by);
                    *reinterpret_cast<float2*>(out + regionOff + (size_t)r0 * LATENT + c0) = v;
                }
                if (r0 + 8 < M) {
                    float2 v = make_float2(acc[mi][ni][2] + bx, acc[mi][ni][3] + by);
                    *reinterpret_cast<float2*>(out + regionOff + (size_t)(r0 + 8) * LATENT + c0) = v;
                }
            } else {
                __half* out = reinterpret_cast<__half*>(outv);
                if (r0 < M) {
                    __half2 h = __floats2half2_rn(acc[mi][ni][0], acc[mi][ni][1]);
                    *reinterpret_cast<__half2*>(out + (size_t)r0 * NHID + col) = h;
                }
                if (r0 + 8 < M) {
                    __half2 h = __floats2half2_rn(acc[mi][ni][2], acc[mi][ni][3]);
                    *reinterpret_cast<__half2*>(out + (size_t)(r0 + 8) * NHID + col) = h;
                }
            }
        }
    }
}

// ===========================================================================
// Prep: transposed fp16 weights + head bias + ZERO g_cnt (fused memset)
// ===========================================================================
__global__ __launch_bounds__(256) void prep_weights(
    const float* __restrict__ gc1_w, const float* __restrict__ gc2_w,
    const float* __restrict__ mu_w, const float* __restrict__ lv_w,
    const float* __restrict__ mu_b, const float* __restrict__ lv_b)
{
    int i = blockIdx.x * blockDim.x + threadIdx.x;
    if (i < NN) g_cnt[i] = 0;
    if (i < NHID * NFEAT) {
        int n = i / NFEAT, k = i % NFEAT;
        g_w1t[i] = __float2half_rn(gc1_w[k * NHID + n]);
    }
    if (i < NHID * NHID) {
        int n = i / NHID, k = i % NHID;
        g_w2t[i] = __float2half_rn(gc2_w[k * NHID + n]);
        g_wct[i] = __float2half_rn(n < LATENT ? mu_w[k * LATENT + n]
                                              : lv_w[k * LATENT + n - LATENT]);
    }
    if (i < NHID)
        g_bcatf[i] = (i < LATENT) ? mu_b[i] : lv_b[i - LATENT];
}

// ===========================================================================
// CSR build
// ===========================================================================
__global__ __launch_bounds__(256) void hist_kernel(const int* __restrict__ ei)
{
    int e = blockIdx.x * blockDim.x + threadIdx.x;
    if (e < EE) atomicAdd(&g_cnt[e < EE ? ei[e] : 0], 1);
}

__global__ __launch_bounds__(256) void scan1_kernel()
{
    __shared__ int sh[256];
    int b = blockIdx.x, t = threadIdx.x;
    int base = b * SCAN_CHUNK + t * 8;
    int v[8];
    int sum = 0;
#pragma unroll
    for (int k = 0; k < 8; k++) {
        int idx = base + k;
        int c = (idx < NN) ? g_cnt[idx] : 0;
        v[k] = sum;
        sum += c;
    }
    sh[t] = sum;
    __syncthreads();
    for (int off = 1; off < 256; off <<= 1) {
        int x = (t >= off) ? sh[t - off] : 0;
        __syncthreads();
        sh[t] += x;
        __syncthreads();
    }
    int threadExcl = sh[t] - sum;
#pragma unroll
    for (int k = 0; k < 8; k++) {
        int idx = base + k;
        if (idx < NTOT) g_rowptr[idx] = threadExcl + v[k];
    }
    if (t == 255) g_blocksums[b] = sh[255];
}

// Merged scan2+scan3: each block adds prefix of blocksums for its chunk.
__global__ __launch_bounds__(256) void scan_fix_kernel()
{
    __shared__ int sh[64];
    int i = blockIdx.x * blockDim.x + threadIdx.x;
    int chunk = (blockIdx.x * 256) / SCAN_CHUNK;      // all 256 idx share one chunk
    int t = threadIdx.x;
    if (t < 64) sh[t] = (t < chunk && t < NSCANBLK) ? g_blocksums[t] : 0;
    __syncthreads();
    // tree-reduce 64 -> 1
    for (int off = 32; off > 0; off >>= 1) {
        if (t < off) sh[t] += sh[t + off];
        __syncthreads();
    }
    if (i < NTOT) g_rowptr[i] += sh[0];
}

// Scatter: atomicAdd directly on rowptr. After completion rowptr[r] = end(r).
__global__ __launch_bounds__(256) void scatter_kernel(
    const int* __restrict__ ei, const float* __restrict__ ew)
{
    int e = blockIdx.x * blockDim.x + threadIdx.x;
    if (e >= EE) return;
    int r = ei[e];
    int pos = atomicAdd(&g_rowptr[r], 1);
    g_colS[pos] = ei[EE + e];
    g_wS[pos]   = ew[e];
}

// ===========================================================================
// CSR SpMM v3: one warp per row; half-warp per edge; metadata pre-loaded
// 16-edges-at-a-time into registers (2 coalesced LDGs) and shfl-broadcast;
// inner loop issues up to 4 independent gathers per half-warp (MLP 4).
// Row r range (shifted convention): [r ? rowptr[r-1] : 0, rowptr[r]).
// ===========================================================================
__global__ __launch_bounds__(256) void spmm_csr_bias_relu(
    const __half* __restrict__ support, const float* __restrict__ bias,
    __half* __restrict__ out)
{
    int row = (blockIdx.x * blockDim.x + threadIdx.x) >> 5;
    if (row >= NN) return;
    const int lane = threadIdx.x & 31;
    const int half = lane >> 4;
    const int sub  = lane & 15;

    const int s = row ? __ldg(&g_rowptr[row - 1]) : 0;
    const int e = __ldg(&g_rowptr[row]);

    float acc[8];
#pragma unroll
    for (int j = 0; j < 8; j++) acc[j] = 0.f;

    const uint4* supv = reinterpret_cast<const uint4*>(support);

    for (int base = s; base < e; base += 16) {
        const int n = min(16, e - base);
        // lanes 0-15 (mirrored in 16-31) load metadata for up to 16 edges
        int   cm = (sub < n) ? __ldg(&g_colS[base + sub]) : 0;
        float wm = (sub < n) ? __ldg(&g_wS[base + sub])   : 0.f;

        int j = 0;
        // 8 edges per step: 4 gathers in flight per half-warp
        for (; j + 8 <= n; j += 8) {
            int   c0 = __shfl_sync(0xFFFFFFFFu, cm, j + 0 + half);
            int   c1 = __shfl_sync(0xFFFFFFFFu, cm, j + 2 + half);
            int   c2 = __shfl_sync(0xFFFFFFFFu, cm, j + 4 + half);
            int   c3 = __shfl_sync(0xFFFFFFFFu, cm, j + 6 + half);
            float w0 = __shfl_sync(0xFFFFFFFFu, wm, j + 0 + half);
            float w1 = __shfl_sync(0xFFFFFFFFu, wm, j + 2 + half);
            float w2 = __shfl_sync(0xFFFFFFFFu, wm, j + 4 + half);
            float w3 = __shfl_sync(0xFFFFFFFFu, wm, j + 6 + half);
            uint4 v0 = __ldg(supv + (size_t)c0 * 16 + sub);
            uint4 v1 = __ldg(supv + (size_t)c1 * 16 + sub);
            uint4 v2 = __ldg(supv + (size_t)c2 * 16 + sub);
            uint4 v3 = __ldg(supv + (size_t)c3 * 16 + sub);
            const __half2* h0 = reinterpret_cast<const __half2*>(&v0);
            const __half2* h1 = reinterpret_cast<const __half2*>(&v1);
            const __half2* h2 = reinterpret_cast<const __half2*>(&v2);
            const __half2* h3 = reinterpret_cast<const __half2*>(&v3);
#pragma unroll
            for (int q = 0; q < 4; q++) {
                float2 f0 = __half22float2(h0[q]);
                float2 f1 = __half22float2(h1[q]);
                float2 f2 = __half22float2(h2[q]);
                float2 f3 = __half22float2(h3[q]);
                acc[2*q+0] = fmaf(w0, f0.x, acc[2*q+0]);
                acc[2*q+1] = fmaf(w0, f0.y, acc[2*q+1]);
                acc[2*q+0] = fmaf(w1, f1.x, acc[2*q+0]);
                acc[2*q+1] = fmaf(w1, f1.y, acc[2*q+1]);
                acc[2*q+0] = fmaf(w2, f2.x, acc[2*q+0]);
                acc[2*q+1] = fmaf(w2, f2.y, acc[2*q+1]);
                acc[2*q+0] = fmaf(w3, f3.x, acc[2*q+0]);
                acc[2*q+1] = fmaf(w3, f3.y, acc[2*q+1]);
            }
        }
        // 2 edges per step
        for (; j + 2 <= n; j += 2) {
            int   c = __shfl_sync(0xFFFFFFFFu, cm, j + half);
            float w = __shfl_sync(0xFFFFFFFFu, wm, j + half);
            uint4 v = __ldg(supv + (size_t)c * 16 + sub);
            const __half2* h = reinterpret_cast<const __half2*>(&v);
#pragma unroll
            for (int q = 0; q < 4; q++) {
                float2 f = __half22float2(h[q]);
                acc[2*q+0] = fmaf(w, f.x, acc[2*q+0]);
                acc[2*q+1] = fmaf(w, f.y, acc[2*q+1]);
            }
        }
        // last odd edge (lanes 0-15 only)
        if (j < n) {
            int   c = __shfl_sync(0xFFFFFFFFu, cm, j);
            float w = __shfl_sync(0xFFFFFFFFu, wm, j);
            if (half == 0) {
                uint4 v = __ldg(supv + (size_t)c * 16 + sub);
                const __half2* h = reinterpret_cast<const __half2*>(&v);
#pragma unroll
                for (int q = 0; q < 4; q++) {
                    float2 f = __half22float2(h[q]);
                    acc[2*q+0] = fmaf(w, f.x, acc[2*q+0]);
                    acc[2*q+1] = fmaf(w, f.y, acc[2*q+1]);
                }
            }
        }
    }

#pragma unroll
    for (int j = 0; j < 8; j++)
        acc[j] += __shfl_down_sync(0xFFFFFFFFu, acc[j], 16);

    if (half == 0) {
        float4 b0 = __ldg(reinterpret_cast<const float4*>(bias) + sub * 2);
        float4 b1 = __ldg(reinterpret_cast<const float4*>(bias) + sub * 2 + 1);
        float r0 = fmaxf(acc[0] + b0.x, 0.f), r1 = fmaxf(acc[1] + b0.y, 0.f);
        float r2 = fmaxf(acc[2] + b0.z, 0.f), r3 = fmaxf(acc[3] + b0.w, 0.f);
        float r4 = fmaxf(acc[4] + b1.x, 0.f), r5 = fmaxf(acc[5] + b1.y, 0.f);
        float r6 = fmaxf(acc[6] + b1.z, 0.f), r7 = fmaxf(acc[7] + b1.w, 0.f);
        __half2 p0 = __floats2half2_rn(r0, r1);
        __half2 p1 = __floats2half2_rn(r2, r3);
        __half2 p2 = __floats2half2_rn(r4, r5);
        __half2 p3 = __floats2half2_rn(r6, r7);
        uint4 st;
        st.x = *reinterpret_cast<uint32_t*>(&p0);
        st.y = *reinterpret_cast<uint32_t*>(&p1);
        st.z = *reinterpret_cast<uint32_t*>(&p2);
        st.w = *reinterpret_cast<uint32_t*>(&p3);
        *(reinterpret_cast<uint4*>(out + (size_t)row * NHID) + sub) = st;
    }
}

// ===========================================================================
extern "C" void kernel_launch(void* const* d_in, const int* in_sizes, int n_in,
                              void* d_out, int out_size)
{
    const float* x      = (const float*)d_in[0];
    const int*   ei     = (const int*)  d_in[1];
    const float* ew     = (const float*)d_in[2];
    const float* gc1_w  = (const float*)d_in[3];
    const float* gc1_b  = (const float*)d_in[4];
    const float* gc2_w  = (const float*)d_in[5];
    const float* gc2_b  = (const float*)d_in[6];
    const float* mu_w   = (const float*)d_in[7];
    const float* mu_b   = (const float*)d_in[8];
    const float* lv_w   = (const float*)d_in[9];
    const float* lv_b   = (const float*)d_in[10];
    float* out = (float*)d_out;

    __half *sup, *h, *w1t, *w2t, *wct;
    float *bcatf;
    cudaGetSymbolAddress((void**)&sup,  g_sup);
    cudaGetSymbolAddress((void**)&h,    g_h);
    cudaGetSymbolAddress((void**)&w1t,  g_w1t);
    cudaGetSymbolAddress((void**)&w2t,  g_w2t);
    cudaGetSymbolAddress((void**)&wct,  g_wct);
    cudaGetSymbolAddress((void**)&bcatf, g_bcatf);

    const int gemmBlocks = (NN + 127) / 128;                 // 782
    const int edgeBlocks = (EE + 255) / 256;
    const int spmmBlocks = (NN * 32 + 255) / 256;

    // ---- Prep (+ zero g_cnt) ----
    prep_weights<<<(NN + 255) / 256, 256>>>(gc1_w, gc2_w, mu_w, lv_w, mu_b, lv_b);

    // ---- CSR build ----
    hist_kernel<<<edgeBlocks, 256>>>(ei);
    scan1_kernel<<<NSCANBLK, 256>>>();
    scan_fix_kernel<<<(NTOT + 255) / 256, 256>>>();
    scatter_kernel<<<edgeBlocks, 256>>>(ei, ew);

    // ---- Layer 1 (A = fp32 x, converted in-loader) ----
    mma_gemm<256, false, true><<<gemmBlocks, 256>>>(x, w1t, nullptr, sup, NN);
    spmm_csr_bias_relu<<<spmmBlocks, 256>>>(sup, gc1_b, h);

    // ---- Layer 2 ----
    mma_gemm<128, false, false><<<gemmBlocks, 256>>>(h, w2t, nullptr, sup, NN);
    spmm_csr_bias_relu<<<spmmBlocks, 256>>>(sup, gc2_b, h);

    // ---- Fused heads ----
    mma_gemm<128, true, false><<<gemmBlocks, 256>>>(h, wct, bcatf, out, NN);
}